// round 2
// baseline (speedup 1.0000x reference)
#include <cuda_runtime.h>

#define BB 8
#define NN 5000
#define EE 100000
#define DD 128
#define NB (BB * NN)        // 40000 target bins
#define NE (BB * EE)        // 800000 edges

// Scratch (allocation-free: __device__ globals)
__device__ int   g_deg[NB];        // edges per target node
__device__ int   g_off[NB];        // exclusive prefix (bin start)
__device__ int   g_cursor[NB];     // fill cursor (starts at g_off)
__device__ int2  g_bin[NE];        // {src, mask_bits} per edge, binned by target
__device__ float g_mean[NB * DD];  // masked mean of neighbor features

// ---------------------------------------------------------------------------
// K0: zero degree counters (160 KB)
// ---------------------------------------------------------------------------
__global__ void zero_deg_kernel() {
    int i = blockIdx.x * blockDim.x + threadIdx.x;
    if (i < NB) g_deg[i] = 0;
}

// ---------------------------------------------------------------------------
// K1: histogram of edge targets
// ---------------------------------------------------------------------------
__global__ void hist_kernel(const int* __restrict__ ei) {
    int idx = blockIdx.x * blockDim.x + threadIdx.x;
    if (idx >= NE) return;
    int b = idx / EE;
    int e = idx - b * EE;
    int tgt = __ldg(&ei[(size_t)b * 2 * EE + EE + e]);
    atomicAdd(&g_deg[b * NN + tgt], 1);
}

// ---------------------------------------------------------------------------
// K2: exclusive prefix sum over 40000 degrees (single block, 1024 threads)
// ---------------------------------------------------------------------------
__global__ void __launch_bounds__(1024, 1) scan_kernel() {
    __shared__ int part[1024];
    const int t = threadIdx.x;
    const int CH = (NB + 1023) / 1024;  // 40
    int lo = t * CH;
    int hi = lo + CH; if (hi > NB) hi = NB;

    int s = 0;
    for (int i = lo; i < hi; ++i) s += g_deg[i];
    part[t] = s;
    __syncthreads();

    // Hillis-Steele inclusive scan over partials
    for (int o = 1; o < 1024; o <<= 1) {
        int v = (t >= o) ? part[t - o] : 0;
        __syncthreads();
        part[t] += v;
        __syncthreads();
    }

    int run = (t > 0) ? part[t - 1] : 0;  // exclusive base for this chunk
    for (int i = lo; i < hi; ++i) {
        g_off[i] = run;
        g_cursor[i] = run;
        run += g_deg[i];
    }
}

// ---------------------------------------------------------------------------
// K3: fill bins. One thread per edge; slot via atomic cursor.
// ---------------------------------------------------------------------------
__global__ void fill_kernel(const int* __restrict__ ei,
                            const float* __restrict__ em) {
    int idx = blockIdx.x * blockDim.x + threadIdx.x;
    if (idx >= NE) return;
    int b = idx / EE;
    int e = idx - b * EE;
    const int* eb = ei + (size_t)b * 2 * EE;
    int src = __ldg(&eb[e]);
    int tgt = __ldg(&eb[EE + e]);
    float m = __ldg(&em[(size_t)b * EE + e]);
    int p = atomicAdd(&g_cursor[b * NN + tgt], 1);
    g_bin[p] = make_int2(src, __float_as_int(m));
}

// ---------------------------------------------------------------------------
// K4: gather. One warp per target node. Lane L owns float4 L of the 128-wide
// row. Edge records are loaded coalesced 32-at-a-time, then broadcast via
// shuffle; accumulation is pure registers — no atomics.
// ---------------------------------------------------------------------------
__global__ void gather_kernel(const float* __restrict__ x) {
    int g = (blockIdx.x * blockDim.x + threadIdx.x) >> 5;  // global node id
    int lane = threadIdx.x & 31;
    if (g >= NB) return;
    int b = g / NN;

    int deg = g_deg[g];
    int off = g_off[g];

    float4 acc = make_float4(0.f, 0.f, 0.f, 0.f);
    float cm = 0.f;

    const float4* x4 = (const float4*)x + (size_t)b * NN * 32;

    for (int base = 0; base < deg; base += 32) {
        int rem = deg - base;
        int chunk = rem < 32 ? rem : 32;
        int2 rec = make_int2(0, 0);
        if (lane < chunk) rec = __ldg(&g_bin[off + base + lane]);

#pragma unroll 4
        for (int j = 0; j < chunk; ++j) {
            int s = __shfl_sync(0xFFFFFFFFu, rec.x, j);
            float m = __int_as_float(__shfl_sync(0xFFFFFFFFu, rec.y, j));
            float4 v = __ldg(&x4[(size_t)s * 32 + lane]);
            acc.x = fmaf(v.x, m, acc.x);
            acc.y = fmaf(v.y, m, acc.y);
            acc.z = fmaf(v.z, m, acc.z);
            acc.w = fmaf(v.w, m, acc.w);
            cm += m;
        }
    }

    float inv = 1.f / fmaxf(cm, 1.f);
    float4 o;
    o.x = acc.x * inv; o.y = acc.y * inv; o.z = acc.z * inv; o.w = acc.w * inv;
    ((float4*)g_mean)[(size_t)g * 32 + lane] = o;
}

// ---------------------------------------------------------------------------
// K5: fused  out = LN(relu(x@Wself + mean@Wnb + b)) * mask
// (same structure as round 1; input tile now reads precomputed means)
// ---------------------------------------------------------------------------
#define TILE_NODES 64
#define FUSED_THREADS 512
#define SMEM_W4 (256 * 32)           // Wc: 256 rows x 32 float4
#define SMEM_IN4 (TILE_NODES * 64)   // inS: 64 nodes x 64 float4 (256 floats)
#define FUSED_SMEM_BYTES ((SMEM_W4 + SMEM_IN4) * 16)

__global__ void __launch_bounds__(FUSED_THREADS, 1)
fused_kernel(const float* __restrict__ x,
             const float* __restrict__ Wself,
             const float* __restrict__ bself,
             const float* __restrict__ Wnb,
             const float* __restrict__ bnb,
             const float* __restrict__ gamma,
             const float* __restrict__ beta,
             const float* __restrict__ nmask,
             float* __restrict__ out) {
    extern __shared__ float4 smem[];
    float4* Wc = smem;                 // [256][32] float4
    float4* inS = smem + SMEM_W4;      // [64][64] float4

    const int tid = threadIdx.x;
    const int cg = tid & 31;   // column group (4 cols)
    const int ng = tid >> 5;   // warp id -> node group (4 nodes)

    const float4* Ws4 = (const float4*)Wself;
    const float4* Wn4 = (const float4*)Wnb;
    for (int i = tid; i < SMEM_W4; i += FUSED_THREADS) {
        int k = i >> 5;
        int c = i & 31;
        Wc[i] = (k < 128) ? Ws4[k * 32 + c] : Wn4[(k - 128) * 32 + c];
    }
    __syncthreads();

    float4 bs = ((const float4*)bself)[cg];
    float4 bn = ((const float4*)bnb)[cg];
    const float bias_x = bs.x + bn.x, bias_y = bs.y + bn.y;
    const float bias_z = bs.z + bn.z, bias_w = bs.w + bn.w;
    const float4 gm = ((const float4*)gamma)[cg];
    const float4 bt = ((const float4*)beta)[cg];

    const int ntiles = NB / TILE_NODES;  // 625
    const float4* x4 = (const float4*)x;
    const float4* m4 = (const float4*)g_mean;

    for (int tile = blockIdx.x; tile < ntiles; tile += gridDim.x) {
        const int node0 = tile * TILE_NODES;

        for (int i = tid; i < SMEM_IN4; i += FUSED_THREADS) {
            int nl = i >> 6;
            int k4 = i & 63;
            int gn = node0 + nl;
            inS[i] = (k4 < 32) ? x4[(size_t)gn * 32 + k4]
                               : m4[(size_t)gn * 32 + (k4 - 32)];
        }
        __syncthreads();

        float4 acc0 = make_float4(bias_x, bias_y, bias_z, bias_w);
        float4 acc1 = acc0, acc2 = acc0, acc3 = acc0;

        const float4* in0 = inS + (ng * 4 + 0) * 64;
        const float4* in1 = inS + (ng * 4 + 1) * 64;
        const float4* in2 = inS + (ng * 4 + 2) * 64;
        const float4* in3 = inS + (ng * 4 + 3) * 64;

#define KSTEP(J, COMP)                                                        \
        {                                                                     \
            float4 w = Wc[(k4 * 4 + J) * 32 + cg];                            \
            acc0.x = fmaf(a0.COMP, w.x, acc0.x);                              \
            acc0.y = fmaf(a0.COMP, w.y, acc0.y);                              \
            acc0.z = fmaf(a0.COMP, w.z, acc0.z);                              \
            acc0.w = fmaf(a0.COMP, w.w, acc0.w);                              \
            acc1.x = fmaf(a1.COMP, w.x, acc1.x);                              \
            acc1.y = fmaf(a1.COMP, w.y, acc1.y);                              \
            acc1.z = fmaf(a1.COMP, w.z, acc1.z);                              \
            acc1.w = fmaf(a1.COMP, w.w, acc1.w);                              \
            acc2.x = fmaf(a2.COMP, w.x, acc2.x);                              \
            acc2.y = fmaf(a2.COMP, w.y, acc2.y);                              \
            acc2.z = fmaf(a2.COMP, w.z, acc2.z);                              \
            acc2.w = fmaf(a2.COMP, w.w, acc2.w);                              \
            acc3.x = fmaf(a3.COMP, w.x, acc3.x);                              \
            acc3.y = fmaf(a3.COMP, w.y, acc3.y);                              \
            acc3.z = fmaf(a3.COMP, w.z, acc3.z);                              \
            acc3.w = fmaf(a3.COMP, w.w, acc3.w);                              \
        }

#pragma unroll 4
        for (int k4 = 0; k4 < 64; ++k4) {
            float4 a0 = in0[k4];
            float4 a1 = in1[k4];
            float4 a2 = in2[k4];
            float4 a3 = in3[k4];
            KSTEP(0, x)
            KSTEP(1, y)
            KSTEP(2, z)
            KSTEP(3, w)
        }
#undef KSTEP

        float4 accs[4] = {acc0, acc1, acc2, acc3};
#pragma unroll
        for (int n = 0; n < 4; ++n) {
            float4 h = accs[n];
            h.x = fmaxf(h.x, 0.f);
            h.y = fmaxf(h.y, 0.f);
            h.z = fmaxf(h.z, 0.f);
            h.w = fmaxf(h.w, 0.f);
            float part = h.x + h.y + h.z + h.w;
#pragma unroll
            for (int o = 16; o > 0; o >>= 1)
                part += __shfl_xor_sync(0xFFFFFFFFu, part, o);
            float mu = part * (1.f / 128.f);
            float dx = h.x - mu, dy = h.y - mu, dz = h.z - mu, dw = h.w - mu;
            float p2 = dx * dx + dy * dy + dz * dz + dw * dw;
#pragma unroll
            for (int o = 16; o > 0; o >>= 1)
                p2 += __shfl_xor_sync(0xFFFFFFFFu, p2, o);
            float rstd = rsqrtf(p2 * (1.f / 128.f) + 1e-5f);

            int gn = node0 + ng * 4 + n;
            float mask = __ldg(&nmask[gn]);
            float4 o4;
            o4.x = (dx * rstd * gm.x + bt.x) * mask;
            o4.y = (dy * rstd * gm.y + bt.y) * mask;
            o4.z = (dz * rstd * gm.z + bt.z) * mask;
            o4.w = (dw * rstd * gm.w + bt.w) * mask;
            ((float4*)out)[(size_t)gn * 32 + cg] = o4;
        }
        __syncthreads();
    }
}

// ---------------------------------------------------------------------------
extern "C" void kernel_launch(void* const* d_in, const int* in_sizes, int n_in,
                              void* d_out, int out_size) {
    const float* x     = (const float*)d_in[0];
    const int*   ei    = (const int*)d_in[1];
    const float* nmask = (const float*)d_in[2];
    const float* emask = (const float*)d_in[3];
    const float* Wself = (const float*)d_in[4];
    const float* bself = (const float*)d_in[5];
    const float* Wnb   = (const float*)d_in[6];
    const float* bnb   = (const float*)d_in[7];
    const float* gamma = (const float*)d_in[8];
    const float* beta  = (const float*)d_in[9];
    float* out = (float*)d_out;

    (void)in_sizes; (void)n_in; (void)out_size;

    zero_deg_kernel<<<(NB + 255) / 256, 256>>>();
    hist_kernel<<<(NE + 255) / 256, 256>>>(ei);
    scan_kernel<<<1, 1024>>>();
    fill_kernel<<<(NE + 255) / 256, 256>>>(ei, emask);
    gather_kernel<<<(NB * 32 + 255) / 256, 256>>>(x);

    cudaFuncSetAttribute(fused_kernel, cudaFuncAttributeMaxDynamicSharedMemorySize,
                         FUSED_SMEM_BYTES);
    int nsm = 148;
    cudaDeviceGetAttribute(&nsm, cudaDevAttrMultiProcessorCount, 0);
    fused_kernel<<<nsm, FUSED_THREADS, FUSED_SMEM_BYTES>>>(
        x, Wself, bself, Wnb, bnb, gamma, beta, nmask, out);
}

// round 3
// speedup vs baseline: 1.2974x; 1.2974x over previous
#include <cuda_runtime.h>

#define BB 8
#define NN 5000
#define EE 100000
#define DD 128
#define NB (BB * NN)        // 40000 target bins
#define NE (BB * EE)        // 800000 edges

typedef unsigned long long u64;

// Scratch (allocation-free: __device__ globals)
__device__ int   g_deg[NB];
__device__ int   g_off[NB];
__device__ int   g_cursor[NB];
__device__ int2  g_bin[NE];        // {src, mask_bits} binned by target
__device__ float g_mean[NB * DD];

// ---------------------------------------------------------------------------
// K0: zero degree counters
// ---------------------------------------------------------------------------
__global__ void zero_deg_kernel() {
    int i = blockIdx.x * blockDim.x + threadIdx.x;
    if (i < NB) g_deg[i] = 0;
}

// ---------------------------------------------------------------------------
// K1: histogram of edge targets
// ---------------------------------------------------------------------------
__global__ void hist_kernel(const int* __restrict__ ei) {
    int idx = blockIdx.x * blockDim.x + threadIdx.x;
    if (idx >= NE) return;
    int b = idx / EE;
    int e = idx - b * EE;
    int tgt = __ldg(&ei[(size_t)b * 2 * EE + EE + e]);
    atomicAdd(&g_deg[b * NN + tgt], 1);
}

// ---------------------------------------------------------------------------
// K2: exclusive prefix sum over 40000 degrees (single block, vectorized)
// ---------------------------------------------------------------------------
__global__ void __launch_bounds__(1024, 1) scan_kernel() {
    __shared__ int part[1024];
    const int t = threadIdx.x;
    const int CH = 40;                   // ints per thread (mult of 4)
    int lo = t * CH;
    if (lo < NB) {
        const int4* d4 = (const int4*)(g_deg + lo);
        int s = 0;
#pragma unroll
        for (int i = 0; i < CH / 4; ++i) {
            int4 v = d4[i];
            s += v.x + v.y + v.z + v.w;
        }
        part[t] = s;
    } else {
        part[t] = 0;
    }
    __syncthreads();

    for (int o = 1; o < 1024; o <<= 1) {
        int v = (t >= o) ? part[t - o] : 0;
        __syncthreads();
        part[t] += v;
        __syncthreads();
    }

    if (lo < NB) {
        int run = (t > 0) ? part[t - 1] : 0;
        const int4* d4 = (const int4*)(g_deg + lo);
        int4* o4 = (int4*)(g_off + lo);
        int4* c4 = (int4*)(g_cursor + lo);
#pragma unroll
        for (int i = 0; i < CH / 4; ++i) {
            int4 v = d4[i];
            int4 w;
            w.x = run; run += v.x;
            w.y = run; run += v.y;
            w.z = run; run += v.z;
            w.w = run; run += v.w;
            o4[i] = w;
            c4[i] = w;
        }
    }
}

// ---------------------------------------------------------------------------
// K3: fill bins (atomic cursor per target)
// ---------------------------------------------------------------------------
__global__ void fill_kernel(const int* __restrict__ ei,
                            const float* __restrict__ em) {
    int idx = blockIdx.x * blockDim.x + threadIdx.x;
    if (idx >= NE) return;
    int b = idx / EE;
    int e = idx - b * EE;
    const int* eb = ei + (size_t)b * 2 * EE;
    int src = __ldg(&eb[e]);
    int tgt = __ldg(&eb[EE + e]);
    float m = __ldg(&em[(size_t)b * EE + e]);
    int p = atomicAdd(&g_cursor[b * NN + tgt], 1);
    g_bin[p] = make_int2(src, __float_as_int(m));
}

// ---------------------------------------------------------------------------
// K4: gather. One warp per target node, lane = float4 column. Edge records
// via uniform broadcast __ldg (no shuffles); explicit 4-wide unroll so the
// rec loads and x-row loads are independent (MLP >= 4).
// ---------------------------------------------------------------------------
__global__ void gather_kernel(const float* __restrict__ x) {
    int g = (blockIdx.x * blockDim.x + threadIdx.x) >> 5;
    int lane = threadIdx.x & 31;
    if (g >= NB) return;
    int b = g / NN;

    const int deg = g_deg[g];
    const int off = g_off[g];
    const float4* x4 = (const float4*)x + (size_t)b * NN * 32;

    float4 acc = make_float4(0.f, 0.f, 0.f, 0.f);
    float cm = 0.f;

    int j = 0;
    for (; j + 4 <= deg; j += 4) {
        int2 r0 = __ldg(&g_bin[off + j]);
        int2 r1 = __ldg(&g_bin[off + j + 1]);
        int2 r2 = __ldg(&g_bin[off + j + 2]);
        int2 r3 = __ldg(&g_bin[off + j + 3]);
        float4 v0 = __ldg(&x4[(size_t)r0.x * 32 + lane]);
        float4 v1 = __ldg(&x4[(size_t)r1.x * 32 + lane]);
        float4 v2 = __ldg(&x4[(size_t)r2.x * 32 + lane]);
        float4 v3 = __ldg(&x4[(size_t)r3.x * 32 + lane]);
        float m0 = __int_as_float(r0.y), m1 = __int_as_float(r1.y);
        float m2 = __int_as_float(r2.y), m3 = __int_as_float(r3.y);
        acc.x = fmaf(v0.x, m0, acc.x); acc.y = fmaf(v0.y, m0, acc.y);
        acc.z = fmaf(v0.z, m0, acc.z); acc.w = fmaf(v0.w, m0, acc.w);
        acc.x = fmaf(v1.x, m1, acc.x); acc.y = fmaf(v1.y, m1, acc.y);
        acc.z = fmaf(v1.z, m1, acc.z); acc.w = fmaf(v1.w, m1, acc.w);
        acc.x = fmaf(v2.x, m2, acc.x); acc.y = fmaf(v2.y, m2, acc.y);
        acc.z = fmaf(v2.z, m2, acc.z); acc.w = fmaf(v2.w, m2, acc.w);
        acc.x = fmaf(v3.x, m3, acc.x); acc.y = fmaf(v3.y, m3, acc.y);
        acc.z = fmaf(v3.z, m3, acc.z); acc.w = fmaf(v3.w, m3, acc.w);
        cm += m0 + m1 + m2 + m3;
    }
    for (; j < deg; ++j) {
        int2 r = __ldg(&g_bin[off + j]);
        float m = __int_as_float(r.y);
        float4 v = __ldg(&x4[(size_t)r.x * 32 + lane]);
        acc.x = fmaf(v.x, m, acc.x); acc.y = fmaf(v.y, m, acc.y);
        acc.z = fmaf(v.z, m, acc.z); acc.w = fmaf(v.w, m, acc.w);
        cm += m;
    }

    float inv = 1.f / fmaxf(cm, 1.f);
    float4 o;
    o.x = acc.x * inv; o.y = acc.y * inv; o.z = acc.z * inv; o.w = acc.w * inv;
    ((float4*)g_mean)[(size_t)g * 32 + lane] = o;
}

// ---------------------------------------------------------------------------
// K5: fused GEMM + relu + LN + mask, using packed fma.rn.f32x2 over the k
// dimension. Weights live in smem TRANSPOSED: WcT[col][k], pitch 260 floats
// (conflict-free LDS.128 for col = cg + 32J). Inputs inS[node][k] are read
// warp-broadcast (all lanes same address). Zero pack instructions.
// ---------------------------------------------------------------------------
#define TILE_NODES 64
#define FUSED_THREADS 512
#define W_PITCH 260                              // floats per WcT row
#define WCT_FLOATS (128 * W_PITCH)               // 33280
#define INS_FLOATS (TILE_NODES * 256)            // 16384
#define FUSED_SMEM_BYTES ((WCT_FLOATS + INS_FLOATS) * 4)

__device__ __forceinline__ void fma2(u64& d, u64 a, u64 b) {
    asm("fma.rn.f32x2 %0, %1, %2, %0;" : "+l"(d) : "l"(a), "l"(b));
}
__device__ __forceinline__ float2 unpack2(u64 v) {
    float2 u;
    asm("mov.b64 {%0, %1}, %2;" : "=f"(u.x), "=f"(u.y) : "l"(v));
    return u;
}

__global__ void __launch_bounds__(FUSED_THREADS, 1)
fused_kernel(const float* __restrict__ x,
             const float* __restrict__ Wself,
             const float* __restrict__ bself,
             const float* __restrict__ Wnb,
             const float* __restrict__ bnb,
             const float* __restrict__ gamma,
             const float* __restrict__ beta,
             const float* __restrict__ nmask,
             float* __restrict__ out) {
    extern __shared__ float smemf[];
    float* WcT = smemf;                 // [128][260]
    float* inS = smemf + WCT_FLOATS;    // [64][256]

    const int tid = threadIdx.x;
    const int cg = tid & 31;   // base column; thread owns cols cg+32J
    const int ng = tid >> 5;   // warp -> 4 nodes

    // Load concatenated transposed weights: WcT[col][k], k<128 self, else nb
    for (int i = tid; i < 256 * 128; i += FUSED_THREADS) {
        int k = i >> 7;
        int col = i & 127;
        float w = (k < 128) ? __ldg(&Wself[k * 128 + col])
                            : __ldg(&Wnb[(k - 128) * 128 + col]);
        WcT[col * W_PITCH + k] = w;
    }
    __syncthreads();

    // Per-thread column constants (cols cg, cg+32, cg+64, cg+96)
    float bias[4], gm[4], bt[4];
#pragma unroll
    for (int J = 0; J < 4; ++J) {
        int c = cg + 32 * J;
        bias[J] = __ldg(&bself[c]) + __ldg(&bnb[c]);
        gm[J] = __ldg(&gamma[c]);
        bt[J] = __ldg(&beta[c]);
    }

    const int ntiles = NB / TILE_NODES;  // 625
    const float4* x4 = (const float4*)x;
    const float4* m4 = (const float4*)g_mean;

    const ulonglong2* wV[4];
#pragma unroll
    for (int J = 0; J < 4; ++J)
        wV[J] = (const ulonglong2*)(WcT + (cg + 32 * J) * W_PITCH);

    for (int tile = blockIdx.x; tile < ntiles; tile += gridDim.x) {
        const int node0 = tile * TILE_NODES;

        // inS[nl][k]: k<128 -> x row, k>=128 -> mean row (float4 granularity)
        for (int i = tid; i < TILE_NODES * 64; i += FUSED_THREADS) {
            int nl = i >> 6;
            int k4 = i & 63;
            int gn = node0 + nl;
            float4 v = (k4 < 32) ? x4[(size_t)gn * 32 + k4]
                                 : m4[(size_t)gn * 32 + (k4 - 32)];
            ((float4*)inS)[(size_t)nl * 64 + k4] = v;
        }
        __syncthreads();

        u64 acc[4][4];
#pragma unroll
        for (int n = 0; n < 4; ++n)
#pragma unroll
            for (int J = 0; J < 4; ++J)
                acc[n][J] = 0ull;

        const ulonglong2* aV[4];
#pragma unroll
        for (int n = 0; n < 4; ++n)
            aV[n] = (const ulonglong2*)(inS + (ng * 4 + n) * 256);

#pragma unroll 2
        for (int k4 = 0; k4 < 64; ++k4) {
            ulonglong2 w0 = wV[0][k4];
            ulonglong2 w1 = wV[1][k4];
            ulonglong2 w2 = wV[2][k4];
            ulonglong2 w3 = wV[3][k4];
#pragma unroll
            for (int n = 0; n < 4; ++n) {
                ulonglong2 a = aV[n][k4];
                fma2(acc[n][0], a.x, w0.x);
                fma2(acc[n][0], a.y, w0.y);
                fma2(acc[n][1], a.x, w1.x);
                fma2(acc[n][1], a.y, w1.y);
                fma2(acc[n][2], a.x, w2.x);
                fma2(acc[n][2], a.y, w2.y);
                fma2(acc[n][3], a.x, w3.x);
                fma2(acc[n][3], a.y, w3.y);
            }
        }

        // Epilogue: relu + LN (warp owns node rows) + affine + mask
#pragma unroll
        for (int n = 0; n < 4; ++n) {
            float h[4];
#pragma unroll
            for (int J = 0; J < 4; ++J) {
                float2 p = unpack2(acc[n][J]);
                h[J] = fmaxf(p.x + p.y + bias[J], 0.f);
            }
            float part = h[0] + h[1] + h[2] + h[3];
#pragma unroll
            for (int o = 16; o > 0; o >>= 1)
                part += __shfl_xor_sync(0xFFFFFFFFu, part, o);
            float mu = part * (1.f / 128.f);
            float d0 = h[0] - mu, d1 = h[1] - mu, d2 = h[2] - mu, d3 = h[3] - mu;
            float p2 = d0 * d0 + d1 * d1 + d2 * d2 + d3 * d3;
#pragma unroll
            for (int o = 16; o > 0; o >>= 1)
                p2 += __shfl_xor_sync(0xFFFFFFFFu, p2, o);
            float rstd = rsqrtf(p2 * (1.f / 128.f) + 1e-5f);

            int gn = node0 + ng * 4 + n;
            float mask = __ldg(&nmask[gn]);
            float* orow = out + (size_t)gn * 128;
            orow[cg +  0] = (d0 * rstd * gm[0] + bt[0]) * mask;
            orow[cg + 32] = (d1 * rstd * gm[1] + bt[1]) * mask;
            orow[cg + 64] = (d2 * rstd * gm[2] + bt[2]) * mask;
            orow[cg + 96] = (d3 * rstd * gm[3] + bt[3]) * mask;
        }
        __syncthreads();
    }
}

// ---------------------------------------------------------------------------
extern "C" void kernel_launch(void* const* d_in, const int* in_sizes, int n_in,
                              void* d_out, int out_size) {
    const float* x     = (const float*)d_in[0];
    const int*   ei    = (const int*)d_in[1];
    const float* nmask = (const float*)d_in[2];
    const float* emask = (const float*)d_in[3];
    const float* Wself = (const float*)d_in[4];
    const float* bself = (const float*)d_in[5];
    const float* Wnb   = (const float*)d_in[6];
    const float* bnb   = (const float*)d_in[7];
    const float* gamma = (const float*)d_in[8];
    const float* beta  = (const float*)d_in[9];
    float* out = (float*)d_out;

    (void)in_sizes; (void)n_in; (void)out_size;

    zero_deg_kernel<<<(NB + 255) / 256, 256>>>();
    hist_kernel<<<(NE + 255) / 256, 256>>>(ei);
    scan_kernel<<<1, 1024>>>();
    fill_kernel<<<(NE + 255) / 256, 256>>>(ei, emask);
    gather_kernel<<<(NB * 32 + 255) / 256, 256>>>(x);

    cudaFuncSetAttribute(fused_kernel, cudaFuncAttributeMaxDynamicSharedMemorySize,
                         FUSED_SMEM_BYTES);
    int nsm = 148;
    cudaDeviceGetAttribute(&nsm, cudaDevAttrMultiProcessorCount, 0);
    fused_kernel<<<nsm, FUSED_THREADS, FUSED_SMEM_BYTES>>>(
        x, Wself, bself, Wnb, bnb, gamma, beta, nmask, out);
}